// round 6
// baseline (speedup 1.0000x reference)
#include <cuda_runtime.h>
#include <cstdint>
#include <math.h>

#define D_DIM 2048
#define B_TOK 4096

// ---------------- scratch (device globals; no allocation allowed) ----------
__device__ float g_srcR[(size_t)B_TOK * D_DIM];
__device__ float g_srcT[(size_t)B_TOK * D_DIM];
__device__ float g_thkR[(size_t)D_DIM * D_DIM];
__device__ float g_thqR[(size_t)D_DIM * D_DIM];
__device__ float g_WR  [(size_t)D_DIM * D_DIM];
__device__ float g_thkT[(size_t)D_DIM * D_DIM];
__device__ float g_S   [(size_t)D_DIM * D_DIM];
__device__ float g_M   [(size_t)D_DIM * D_DIM];
__device__ float g_T1  [(size_t)D_DIM * D_DIM];
__device__ float g_MT  [(size_t)D_DIM * D_DIM];
__device__ float g_T1T [(size_t)D_DIM * D_DIM];
__device__ float g_Wn  [(size_t)D_DIM * D_DIM];
__device__ float g_P   [(size_t)D_DIM * D_DIM];
__device__ float g_PT  [(size_t)D_DIM * D_DIM];
__device__ float g_part[32 * D_DIM];
__device__ float g_c   [D_DIM];
__device__ float g_v   [D_DIM];
__device__ float g_bn  [D_DIM];

// ---------------- PTX helpers ----------------------------------------------
__device__ __forceinline__ float rnd_tf32(float x) {
    uint32_t r;
    asm("cvt.rna.tf32.f32 %0, %1;" : "=r"(r) : "f"(x));
    return __uint_as_float(r);
}

__device__ __forceinline__ void cp16(uint32_t dst, const float* src) {
    asm volatile("cp.async.cg.shared.global [%0], [%1], 16;" :: "r"(dst), "l"(src));
}

__device__ __forceinline__ void ldsm4(uint32_t& r0, uint32_t& r1, uint32_t& r2, uint32_t& r3,
                                      uint32_t addr) {
    asm volatile("ldmatrix.sync.aligned.m8n8.x4.shared.b16 {%0,%1,%2,%3}, [%4];"
                 : "=r"(r0), "=r"(r1), "=r"(r2), "=r"(r3) : "r"(addr));
}

__device__ __forceinline__ void mma_tf32(float c[4], const uint32_t a[4],
                                         uint32_t b0, uint32_t b1) {
    asm volatile(
        "mma.sync.aligned.m16n8k8.row.col.f32.tf32.tf32.f32 "
        "{%0,%1,%2,%3}, {%4,%5,%6,%7}, {%8,%9}, {%0,%1,%2,%3};"
        : "+f"(c[0]), "+f"(c[1]), "+f"(c[2]), "+f"(c[3])
        : "r"(a[0]), "r"(a[1]), "r"(a[2]), "r"(a[3]), "r"(b0), "r"(b1));
}

// ---------------------------------------------------------------------------
// NT tf32 tensor GEMM:  C[M,N] = A[M,K] * B[N,K]^T  (+ fused epilogues)
// Inputs MUST be pre-rounded to tf32 (RNA) — mainloop has no cvt.
// CTA 128x128, BK=32, 3-stage cp.async (96KB -> 2 CTAs/SM), 8 warps of 64x32.
// EPI 0: C = acc
// EPI 1: C = acc + e1[idx] - e2[idx]
// EPI 2: C = e1[idx] - e2[idx] * coef * (acc + ev0[row]*ev1[col])
// EPI 3: C = acc + e1[idx]
// EPI 4: C = acc + e0[col]
// SYM: C symmetric (A==B); grid.x = 136 lower-triangle tiles; mirror blocks.
// ---------------------------------------------------------------------------
template <int EPI, bool RND, bool SYM>
__global__ void __launch_bounds__(256, 2)
ntgemm(const float* __restrict__ A, const float* __restrict__ B,
       float* __restrict__ C, int M, int N, int K,
       const float* __restrict__ e0, const float* __restrict__ e1,
       const float* __restrict__ e2, const float* __restrict__ ev0,
       const float* __restrict__ ev1, float coef)
{
    constexpr int BK   = 32;
    constexpr int TILE = 128 * BK * 4;   // 16 KB per operand tile
    constexpr int SS   = 2 * TILE;       // 32 KB per stage

    extern __shared__ __align__(128) char smraw[];
    const uint32_t sb = (uint32_t)__cvta_generic_to_shared(smraw);

    const int tid  = threadIdx.x;
    const int lane = tid & 31;
    const int wid  = tid >> 5;
    const int wm   = (wid & 1) * 64;
    const int wn   = (wid >> 1) * 32;

    int bx, by;
    if (SYM) {
        const int i = blockIdx.x;
        int e = (int)((sqrtf(8.0f * (float)i + 1.0f) - 1.0f) * 0.5f);
        while ((e + 1) * (e + 2) / 2 <= i) ++e;
        while (e * (e + 1) / 2 > i) --e;
        by = e;
        bx = i - e * (e + 1) / 2;
    } else {
        bx = blockIdx.x;
        by = blockIdx.y;
    }
    const int m0 = by * 128;
    const int n0 = bx * 128;

    // ---- global->smem loader mapping (XOR-swizzled 16B chunks) ----
    const int lr = tid >> 3;            // 0..31 (row base; +32*i)
    const int lc = tid & 7;             // chunk 0..7
    const uint32_t lOff = (uint32_t)(lr * 128 + ((lc ^ (lr & 7)) << 4));
    const float* aG = A + (size_t)(m0 + lr) * K + lc * 4;
    const float* bG = B + (size_t)(n0 + lr) * K + lc * 4;

    auto loadTile = [&](int t) {
        const uint32_t base = sb + (uint32_t)((t % 3) * SS);
        const float* a = aG + (size_t)t * BK;
        const float* b = bG + (size_t)t * BK;
#pragma unroll
        for (int i = 0; i < 4; ++i)
            cp16(base + lOff + 4096u * i, a + (size_t)(32 * i) * K);
#pragma unroll
        for (int i = 0; i < 4; ++i)
            cp16(base + TILE + lOff + 4096u * i, b + (size_t)(32 * i) * K);
        asm volatile("cp.async.commit_group;" ::: "memory");
    };

    // ---- ldmatrix addressing (precomputed) ----
    const int rr  = lane & 7;
    const int loA = (lane >> 3) & 1;
    const int hiA = (lane >> 4) & 1;
    const int loB = (lane >> 4) & 1;
    const int hiB = (lane >> 3) & 1;
    const uint32_t swz = (uint32_t)rr << 4;

    uint32_t aRow[4], bRow[2];
#pragma unroll
    for (int mf = 0; mf < 4; ++mf)
        aRow[mf] = (uint32_t)((wm + mf * 16 + loA * 8 + rr) * 128);
#pragma unroll
    for (int nfp = 0; nfp < 2; ++nfp)
        bRow[nfp] = (uint32_t)((wn + nfp * 16 + loB * 8 + rr) * 128);

    float acc[4][4][4];
#pragma unroll
    for (int i = 0; i < 4; ++i)
#pragma unroll
        for (int j = 0; j < 4; ++j)
#pragma unroll
            for (int k = 0; k < 4; ++k) acc[i][j][k] = 0.0f;

    const int nt = K / BK;
    loadTile(0);
    loadTile(1);

    for (int t = 0; t < nt; ++t) {
        if (t + 1 < nt) asm volatile("cp.async.wait_group 1;" ::: "memory");
        else            asm volatile("cp.async.wait_group 0;" ::: "memory");
        __syncthreads();
        if (t + 2 < nt) loadTile(t + 2);

        const uint32_t stA = sb + (uint32_t)((t % 3) * SS);
        const uint32_t stB = stA + TILE;

#pragma unroll
        for (int kk = 0; kk < 4; ++kk) {
            const uint32_t ak = (((uint32_t)(2 * kk + hiA)) << 4) ^ swz;
            const uint32_t bk = (((uint32_t)(2 * kk + hiB)) << 4) ^ swz;
            uint32_t af[4][4];
#pragma unroll
            for (int mf = 0; mf < 4; ++mf)
                ldsm4(af[mf][0], af[mf][1], af[mf][2], af[mf][3], stA + aRow[mf] + ak);
            uint32_t bf[2][4];
#pragma unroll
            for (int nfp = 0; nfp < 2; ++nfp)
                ldsm4(bf[nfp][0], bf[nfp][1], bf[nfp][2], bf[nfp][3], stB + bRow[nfp] + bk);
#pragma unroll
            for (int mf = 0; mf < 4; ++mf)
#pragma unroll
                for (int nf = 0; nf < 4; ++nf)
                    mma_tf32(acc[mf][nf], af[mf],
                             bf[nf >> 1][(nf & 1) * 2], bf[nf >> 1][(nf & 1) * 2 + 1]);
        }
    }

    // ---- epilogue ----
    const int g   = lane >> 2;
    const int tig = lane & 3;
#pragma unroll
    for (int mf = 0; mf < 4; ++mf) {
#pragma unroll
        for (int nf = 0; nf < 4; ++nf) {
#pragma unroll
            for (int h = 0; h < 2; ++h) {
                const int r = m0 + wm + mf * 16 + g + h * 8;
                const int c = n0 + wn + nf * 8 + 2 * tig;
                const size_t idx = (size_t)r * N + c;
                float v0 = acc[mf][nf][h * 2 + 0];
                float v1 = acc[mf][nf][h * 2 + 1];
                if (EPI == 1) {
                    const float2 a1 = *reinterpret_cast<const float2*>(e1 + idx);
                    const float2 a2 = *reinterpret_cast<const float2*>(e2 + idx);
                    v0 += a1.x - a2.x;
                    v1 += a1.y - a2.y;
                } else if (EPI == 2) {
                    const float2 w  = *reinterpret_cast<const float2*>(e1 + idx);
                    const float2 lr = *reinterpret_cast<const float2*>(e2 + idx);
                    const float bi  = ev0[r];
                    const float g0  = coef * (v0 + bi * ev1[c]);
                    const float g1  = coef * (v1 + bi * ev1[c + 1]);
                    v0 = w.x - lr.x * g0;
                    v1 = w.y - lr.y * g1;
                } else if (EPI == 3) {
                    const float2 a1 = *reinterpret_cast<const float2*>(e1 + idx);
                    v0 += a1.x;
                    v1 += a1.y;
                } else if (EPI == 4) {
                    v0 += e0[c];
                    v1 += e0[c + 1];
                }
                if (RND) { v0 = rnd_tf32(v0); v1 = rnd_tf32(v1); }
                float2 out; out.x = v0; out.y = v1;
                *reinterpret_cast<float2*>(C + idx) = out;
            }
        }
    }

    // ---- symmetric mirror: write block (bx, by) = transpose of this block ----
    if (SYM && bx != by) {
        __syncthreads();
        float* esm = reinterpret_cast<float*>(smraw);   // 128 x 132 staging
#pragma unroll
        for (int mf = 0; mf < 4; ++mf) {
#pragma unroll
            for (int nf = 0; nf < 4; ++nf) {
#pragma unroll
                for (int h = 0; h < 2; ++h) {
                    const int rl = wm + mf * 16 + g + h * 8;
                    const int cl = wn + nf * 8 + 2 * tig;
                    float v0 = acc[mf][nf][h * 2 + 0];
                    float v1 = acc[mf][nf][h * 2 + 1];
                    if (RND) { v0 = rnd_tf32(v0); v1 = rnd_tf32(v1); }
                    esm[(cl + 0) * 132 + rl] = v0;
                    esm[(cl + 1) * 132 + rl] = v1;
                }
            }
        }
        __syncthreads();
#pragma unroll
        for (int i = 0; i < 16; ++i) {
            const int chunk = tid + (i << 8);
            const int row  = chunk >> 5;          // 0..127
            const int col4 = (chunk & 31) << 2;   // 0..124
            const float4 v = *reinterpret_cast<const float4*>(esm + row * 132 + col4);
            *reinterpret_cast<float4*>(C + (size_t)(n0 + row) * N + m0 + col4) = v;
        }
    }
}

// ---------------- small kernels ----------------------------------------------
__global__ void round_kernel(const float* __restrict__ in, float* __restrict__ out, int n4)
{
    int i = blockIdx.x * blockDim.x + threadIdx.x;
    if (i < n4) {
        float4 v = reinterpret_cast<const float4*>(in)[i];
        v.x = rnd_tf32(v.x); v.y = rnd_tf32(v.y);
        v.z = rnd_tf32(v.z); v.w = rnd_tf32(v.w);
        reinterpret_cast<float4*>(out)[i] = v;
    }
}

// Dual output: outR[r,c] = rnd(in[r,c]); outT[c,r] = rnd(in[r,c]).
// grid (C/32, R/32), block (32, 8)
__global__ void round_and_T(const float* __restrict__ in, float* __restrict__ outR,
                            float* __restrict__ outT, int R, int C)
{
    __shared__ float tile[32][33];
    const int bx = blockIdx.x * 32, by = blockIdx.y * 32;
    const int x = threadIdx.x, y = threadIdx.y;
#pragma unroll
    for (int j = 0; j < 32; j += 8) {
        const float v = rnd_tf32(in[(size_t)(by + y + j) * C + bx + x]);
        tile[y + j][x] = v;
        outR[(size_t)(by + y + j) * C + bx + x] = v;
    }
    __syncthreads();
#pragma unroll
    for (int j = 0; j < 32; j += 8)
        outT[(size_t)(bx + y + j) * R + by + x] = tile[x][y + j];
}

// out[c, r] = rnd(in[r, c]); in is [R, C]; grid (C/32, R/32), block (32, 8)
__global__ void transpose_round(const float* __restrict__ in, float* __restrict__ out,
                                int R, int C)
{
    __shared__ float tile[32][33];
    const int bx = blockIdx.x * 32, by = blockIdx.y * 32;
    const int x = threadIdx.x, y = threadIdx.y;
#pragma unroll
    for (int j = 0; j < 32; j += 8)
        tile[y + j][x] = in[(size_t)(by + y + j) * C + bx + x];
    __syncthreads();
#pragma unroll
    for (int j = 0; j < 32; j += 8)
        out[(size_t)(bx + y + j) * R + by + x] = rnd_tf32(tile[x][y + j]);
}

// partial column sums over 128-row chunks (src is [4096, 2048])
__global__ void colsum_kernel(const float* __restrict__ in, float* __restrict__ part)
{
    int col = blockIdx.x * blockDim.x + threadIdx.x;
    int chunk = blockIdx.y;
    const float* p = in + (size_t)chunk * 128 * D_DIM + col;
    float s0 = 0.f, s1 = 0.f, s2 = 0.f, s3 = 0.f;
#pragma unroll
    for (int r = 0; r < 128; r += 4) {
        s0 += p[(size_t)(r + 0) * D_DIM];
        s1 += p[(size_t)(r + 1) * D_DIM];
        s2 += p[(size_t)(r + 2) * D_DIM];
        s3 += p[(size_t)(r + 3) * D_DIM];
    }
    part[chunk * D_DIM + col] = (s0 + s1) + (s2 + s3);
}

__global__ void creduce_kernel(const float* __restrict__ part, float* __restrict__ c)
{
    int j = blockIdx.x * blockDim.x + threadIdx.x;
    float s = 0.f;
#pragma unroll
    for (int ch = 0; ch < 32; ++ch) s += part[ch * D_DIM + j];
    c[j] = s;
}

// outv[j] = sum_k vec[k] * Mat[k, j]
__global__ void vecmat_kernel(const float* __restrict__ vec, const float* __restrict__ Mat,
                              float* __restrict__ outv)
{
    int j = blockIdx.x * blockDim.x + threadIdx.x;
    float s0 = 0.f, s1 = 0.f, s2 = 0.f, s3 = 0.f;
#pragma unroll 4
    for (int k = 0; k < D_DIM; k += 4) {
        s0 += vec[k + 0] * Mat[(size_t)(k + 0) * D_DIM + j];
        s1 += vec[k + 1] * Mat[(size_t)(k + 1) * D_DIM + j];
        s2 += vec[k + 2] * Mat[(size_t)(k + 2) * D_DIM + j];
        s3 += vec[k + 3] * Mat[(size_t)(k + 3) * D_DIM + j];
    }
    outv[j] = (s0 + s1) + (s2 + s3);
}

// bn[j] = b[j] - lr_b[j] * coef * ( (c @ M)[j] + B_TOK * b[j] )
__global__ void bn_kernel(const float* __restrict__ Mm, const float* __restrict__ c,
                          const float* __restrict__ b, const float* __restrict__ lrb,
                          float* __restrict__ bn, float coef)
{
    int j = blockIdx.x * blockDim.x + threadIdx.x;
    float s0 = 0.f, s1 = 0.f, s2 = 0.f, s3 = 0.f;
#pragma unroll 4
    for (int k = 0; k < D_DIM; k += 4) {
        s0 += c[k + 0] * Mm[(size_t)(k + 0) * D_DIM + j];
        s1 += c[k + 1] * Mm[(size_t)(k + 1) * D_DIM + j];
        s2 += c[k + 2] * Mm[(size_t)(k + 2) * D_DIM + j];
        s3 += c[k + 3] * Mm[(size_t)(k + 3) * D_DIM + j];
    }
    float s = (s0 + s1) + (s2 + s3);
    bn[j] = b[j] - lrb[j] * coef * (s + (float)B_TOK * b[j]);
}

// ---------------- host --------------------------------------------------------
extern "C" void kernel_launch(void* const* d_in, const int* in_sizes, int n_in,
                              void* d_out, int out_size)
{
    const float* src  = (const float*)d_in[0];
    const float* th_k = (const float*)d_in[1];
    const float* th_q = (const float*)d_in[2];
    const float* th_v = (const float*)d_in[3];
    const float* W    = (const float*)d_in[4];
    const float* b    = (const float*)d_in[5];
    const float* lr_w = (const float*)d_in[6];
    const float* lr_b = (const float*)d_in[7];
    float* out = (float*)d_out;

    float *srcR, *srcT, *thkR, *thqR, *WR, *thkT, *S, *Mm, *T1, *MT, *T1T, *Wn, *P, *PT;
    float *part, *cvec, *vvec, *bn;
    cudaGetSymbolAddress((void**)&srcR, g_srcR);
    cudaGetSymbolAddress((void**)&srcT, g_srcT);
    cudaGetSymbolAddress((void**)&thkR, g_thkR);
    cudaGetSymbolAddress((void**)&thqR, g_thqR);
    cudaGetSymbolAddress((void**)&WR,   g_WR);
    cudaGetSymbolAddress((void**)&thkT, g_thkT);
    cudaGetSymbolAddress((void**)&S,    g_S);
    cudaGetSymbolAddress((void**)&Mm,   g_M);
    cudaGetSymbolAddress((void**)&T1,   g_T1);
    cudaGetSymbolAddress((void**)&MT,   g_MT);
    cudaGetSymbolAddress((void**)&T1T,  g_T1T);
    cudaGetSymbolAddress((void**)&Wn,   g_Wn);
    cudaGetSymbolAddress((void**)&P,    g_P);
    cudaGetSymbolAddress((void**)&PT,   g_PT);
    cudaGetSymbolAddress((void**)&part, g_part);
    cudaGetSymbolAddress((void**)&cvec, g_c);
    cudaGetSymbolAddress((void**)&vvec, g_v);
    cudaGetSymbolAddress((void**)&bn,   g_bn);

    const float coef = 2.0f / ((float)B_TOK * (float)D_DIM);
    const int SMEM = 3 * 2 * 128 * 32 * 4;   // 98304 (3 stages)

    cudaFuncSetAttribute(ntgemm<0, true,  true >, cudaFuncAttributeMaxDynamicSharedMemorySize, SMEM);
    cudaFuncSetAttribute(ntgemm<0, false, false>, cudaFuncAttributeMaxDynamicSharedMemorySize, SMEM);
    cudaFuncSetAttribute(ntgemm<1, true,  false>, cudaFuncAttributeMaxDynamicSharedMemorySize, SMEM);
    cudaFuncSetAttribute(ntgemm<2, true,  false>, cudaFuncAttributeMaxDynamicSharedMemorySize, SMEM);
    cudaFuncSetAttribute(ntgemm<3, false, false>, cudaFuncAttributeMaxDynamicSharedMemorySize, SMEM);
    cudaFuncSetAttribute(ntgemm<4, false, false>, cudaFuncAttributeMaxDynamicSharedMemorySize, SMEM);

    dim3 tb(32, 8);

    // prep: fused round+transpose for src and theta_k; rounded copies for others
    round_and_T<<<dim3(D_DIM / 32, B_TOK / 32), tb>>>(src, srcR, srcT, B_TOK, D_DIM);
    round_and_T<<<dim3(D_DIM / 32, D_DIM / 32), tb>>>(th_k, thkR, thkT, D_DIM, D_DIM);
    round_kernel<<<(D_DIM * D_DIM / 4 + 255) / 256, 256>>>(th_q, thqR, D_DIM * D_DIM / 4);
    round_kernel<<<(D_DIM * D_DIM / 4 + 255) / 256, 256>>>(W, WR, D_DIM * D_DIM / 4);

    // column sums of src -> c ; v = c @ theta_k
    colsum_kernel<<<dim3(D_DIM / 256, 32), 256>>>(src, part);
    creduce_kernel<<<D_DIM / 256, 256>>>(part, cvec);
    vecmat_kernel<<<D_DIM / 128, 128>>>(cvec, th_k, vvec);

    dim3 gridD(D_DIM / 128, D_DIM / 128);   // (16, 16)
    dim3 gridB(D_DIM / 128, B_TOK / 128);   // (16, 32)
    const int nSymTiles = (D_DIM / 128) * (D_DIM / 128 + 1) / 2;   // 136

    // S = src^T @ src   (symmetric: lower-triangle tiles + mirror)
    ntgemm<0, true,  true ><<<nSymTiles, 256, SMEM>>>(srcT, srcT, S, D_DIM, D_DIM, B_TOK,
                                                      nullptr, nullptr, nullptr, nullptr, nullptr, 0.f);
    // M = theta_k @ W^T + theta_k - theta_v
    ntgemm<1, true,  false><<<gridD, 256, SMEM>>>(thkR, WR, Mm, D_DIM, D_DIM, D_DIM,
                                                  nullptr, th_k, th_v, nullptr, nullptr, 0.f);
    // T1 = S @ theta_k   (NT with thkT)
    ntgemm<0, false, false><<<gridD, 256, SMEM>>>(S, thkT, T1, D_DIM, D_DIM, D_DIM,
                                                  nullptr, nullptr, nullptr, nullptr, nullptr, 0.f);
    transpose_round<<<dim3(D_DIM / 32, D_DIM / 32), tb>>>(Mm, MT, D_DIM, D_DIM);
    transpose_round<<<dim3(D_DIM / 32, D_DIM / 32), tb>>>(T1, T1T, D_DIM, D_DIM);

    // Wn = W - lr_w * coef * (M^T @ T1 + b (x) v)
    ntgemm<2, true,  false><<<gridD, 256, SMEM>>>(MT, T1T, Wn, D_DIM, D_DIM, D_DIM,
                                                  nullptr, W, lr_w, b, vvec, coef);
    // bn = b - lr_b * coef * (c @ M + B*b)
    bn_kernel<<<D_DIM / 128, 128>>>(Mm, cvec, b, lr_b, bn, coef);

    // P = theta_q @ Wn^T + theta_q
    ntgemm<3, false, false><<<gridD, 256, SMEM>>>(thqR, Wn, P, D_DIM, D_DIM, D_DIM,
                                                  nullptr, th_q, nullptr, nullptr, nullptr, 0.f);
    transpose_round<<<dim3(D_DIM / 32, D_DIM / 32), tb>>>(P, PT, D_DIM, D_DIM);

    // z = src @ P + bn
    ntgemm<4, false, false><<<gridB, 256, SMEM>>>(srcR, PT, out, B_TOK, D_DIM, D_DIM,
                                                  bn, nullptr, nullptr, nullptr, nullptr, 0.f);
}